// round 1
// baseline (speedup 1.0000x reference)
#include <cuda_runtime.h>
#include <cstddef>

#define QLEN 1024
#define BSZ 8
#define DMODEL 512
#define NHEAD 8
#define DHEAD 64

// ---------------- scratch (device globals: allocation-free) ----------------
__device__ float g_wheads[QLEN * BSZ * 3 * DMODEL]; // [q][b][1536]  q|k|v each n*64+d
__device__ float g_rk[QLEN * DMODEL];               // [p][n*64+d]
__device__ float g_bk[BSZ * NHEAD * QLEN];          // [(b*8+n)][j] = rwb_n . k_jbn
__device__ float g_br[NHEAD * QLEN];                // [n][p]       = rrb_n . rk_pn
__device__ float g_av[QLEN * BSZ * DMODEL];         // attn_vec [q][b][n*64+d]
__device__ float g_ao[QLEN * BSZ * DMODEL];         // attn_out

// ---------------- generic SGEMM: C[M,N] = A[M,K] * B[K,N] ------------------
// 64x64 tile, BK=16, 256 threads, 4x4 microtile. Row-major, dims mult of 64/16.
__global__ __launch_bounds__(256) void sgemm_k(
    const float* __restrict__ A, int lda,
    const float* __restrict__ B, int ldb,
    float* __restrict__ C, int ldc, int K)
{
    __shared__ float As[16][68]; // transposed: As[k][m]
    __shared__ float Bs[16][68]; // Bs[k][n]
    const int m0 = blockIdx.y * 64, n0 = blockIdx.x * 64;
    const int tid = threadIdx.x;
    const int ty = tid >> 4, tx = tid & 15;
    const int ar = tid >> 2, akq = (tid & 3) << 2; // A: row, k-quad

    float acc[4][4];
#pragma unroll
    for (int i = 0; i < 4; i++)
#pragma unroll
        for (int j = 0; j < 4; j++) acc[i][j] = 0.f;

    for (int k0 = 0; k0 < K; k0 += 16) {
        float4 a4 = *(const float4*)&A[(size_t)(m0 + ar) * lda + k0 + akq];
        float4 b4 = *(const float4*)&B[(size_t)(k0 + ty) * ldb + n0 + tx * 4];
        __syncthreads();
        As[akq + 0][ar] = a4.x; As[akq + 1][ar] = a4.y;
        As[akq + 2][ar] = a4.z; As[akq + 3][ar] = a4.w;
        *(float4*)&Bs[ty][tx * 4] = b4;
        __syncthreads();
#pragma unroll
        for (int kk = 0; kk < 16; ++kk) {
            float4 a = *(float4*)&As[kk][ty * 4];
            float4 b = *(float4*)&Bs[kk][tx * 4];
            acc[0][0] = fmaf(a.x, b.x, acc[0][0]); acc[0][1] = fmaf(a.x, b.y, acc[0][1]);
            acc[0][2] = fmaf(a.x, b.z, acc[0][2]); acc[0][3] = fmaf(a.x, b.w, acc[0][3]);
            acc[1][0] = fmaf(a.y, b.x, acc[1][0]); acc[1][1] = fmaf(a.y, b.y, acc[1][1]);
            acc[1][2] = fmaf(a.y, b.z, acc[1][2]); acc[1][3] = fmaf(a.y, b.w, acc[1][3]);
            acc[2][0] = fmaf(a.z, b.x, acc[2][0]); acc[2][1] = fmaf(a.z, b.y, acc[2][1]);
            acc[2][2] = fmaf(a.z, b.z, acc[2][2]); acc[2][3] = fmaf(a.z, b.w, acc[2][3]);
            acc[3][0] = fmaf(a.w, b.x, acc[3][0]); acc[3][1] = fmaf(a.w, b.y, acc[3][1]);
            acc[3][2] = fmaf(a.w, b.z, acc[3][2]); acc[3][3] = fmaf(a.w, b.w, acc[3][3]);
        }
    }
#pragma unroll
    for (int i = 0; i < 4; i++) {
        float4 o; o.x = acc[i][0]; o.y = acc[i][1]; o.z = acc[i][2]; o.w = acc[i][3];
        *(float4*)&C[(size_t)(m0 + ty * 4 + i) * ldc + n0 + tx * 4] = o;
    }
}

// ---------------- bias precompute: bk[b][n][j] = rwb_n . K_jbn -------------
__global__ __launch_bounds__(256) void biask_kernel(const float* __restrict__ rwb)
{
    int id = blockIdx.x * 8 + (threadIdx.x >> 5); // (b*8+n)*1024 + j
    int lane = threadIdx.x & 31;
    int j = id & 1023;
    int bn = id >> 10;
    int b = bn >> 3, n = bn & 7;
    const float* base = g_wheads + ((size_t)j * BSZ + b) * 1536 + 512 + n * 64;
    const float* wv = rwb + n * 64;
    float v = wv[lane] * base[lane] + wv[lane + 32] * base[lane + 32];
#pragma unroll
    for (int o = 16; o >= 1; o >>= 1) v += __shfl_xor_sync(0xffffffffu, v, o);
    if (lane == 0) g_bk[id] = v;
}

__global__ __launch_bounds__(256) void biasr_kernel(const float* __restrict__ rrb)
{
    int id = blockIdx.x * 8 + (threadIdx.x >> 5); // n*1024 + p
    int lane = threadIdx.x & 31;
    int p = id & 1023;
    int n = id >> 10;
    const float* base = g_rk + (size_t)p * DMODEL + n * 64;
    const float* wv = rrb + n * 64;
    float v = wv[lane] * base[lane] + wv[lane + 32] * base[lane + 32];
#pragma unroll
    for (int o = 16; o >= 1; o >>= 1) v += __shfl_xor_sync(0xffffffffu, v, o);
    if (lane == 0) g_br[id] = v;
}

// ---------------- fused causal attention with rel-shift --------------------
// Grid (16 i-tiles, 64 bn). 256 threads, 4x4 microtile over 64x64 score tiles.
// S[i,j] = (q_i.k_j + bk[j] + q_i.rk_p + br[p]) * 0.125, p = 1023 - i + j, j<=i.
__global__ __launch_bounds__(256) void attn_kernel(float* __restrict__ av)
{
    extern __shared__ float smf[];
    float* Qs  = smf;             // 64*65
    float* Ks  = Qs + 64 * 65;
    float* Vs  = Ks + 64 * 65;
    float* RKs = Vs + 64 * 65;    // 128*65 (slab t=0..126)
    float* Ps  = RKs + 128 * 65;  // 64*65
    float* bks = Ps + 64 * 65;    // 64
    float* brs = bks + 64;        // 128

    const int i0 = blockIdx.x * 64;
    const int bn = blockIdx.y;
    const int b = bn >> 3, n = bn & 7;
    const int tid = threadIdx.x;
    const int ty = tid >> 4, tx = tid & 15;
    const int tbase = 63 + 4 * (tx - ty); // t for (ii=0,jj=0); t(ii,jj)=tbase+jj-ii in [0,126]

    // Q tile
    for (int idx = tid; idx < 64 * 16; idx += 256) {
        int r = idx >> 4, q4 = (idx & 15) << 2;
        float4 v = *(const float4*)(g_wheads + ((size_t)(i0 + r) * BSZ + b) * 1536 + n * 64 + q4);
        float* dst = Qs + r * 65 + q4;
        dst[0] = v.x; dst[1] = v.y; dst[2] = v.z; dst[3] = v.w;
    }

    float m[4], l[4], acc[4][4];
#pragma unroll
    for (int i = 0; i < 4; i++) {
        m[i] = -1e30f; l[i] = 0.f;
#pragma unroll
        for (int j = 0; j < 4; j++) acc[i][j] = 0.f;
    }

    const int ntiles = i0 / 64 + 1;
    for (int jt = 0; jt < ntiles; ++jt) {
        const int j0 = jt * 64;
        const int pmin = (QLEN - 64) - i0 + j0; // 960 - i0 + j0, always >= 0
        __syncthreads();
        // K, V tiles
        for (int idx = tid; idx < 64 * 16; idx += 256) {
            int r = idx >> 4, q4 = (idx & 15) << 2;
            const float* srcK = g_wheads + ((size_t)(j0 + r) * BSZ + b) * 1536 + 512 + n * 64 + q4;
            float4 k4 = *(const float4*)srcK;
            float4 v4 = *(const float4*)(srcK + 512);
            float* dK = Ks + r * 65 + q4;
            dK[0] = k4.x; dK[1] = k4.y; dK[2] = k4.z; dK[3] = k4.w;
            float* dV = Vs + r * 65 + q4;
            dV[0] = v4.x; dV[1] = v4.y; dV[2] = v4.z; dV[3] = v4.w;
        }
        // RK slab (rows t=0..127, p clamped; clamped rows only feed masked entries)
        for (int idx = tid; idx < 128 * 16; idx += 256) {
            int t = idx >> 4, q4 = (idx & 15) << 2;
            int p = pmin + t; if (p > QLEN - 1) p = QLEN - 1;
            float4 v = *(const float4*)(g_rk + (size_t)p * DMODEL + n * 64 + q4);
            float* dst = RKs + t * 65 + q4;
            dst[0] = v.x; dst[1] = v.y; dst[2] = v.z; dst[3] = v.w;
        }
        if (tid < 64) bks[tid] = g_bk[((size_t)b * 8 + n) * 1024 + j0 + tid];
        if (tid < 128) { int p = pmin + tid; if (p > 1023) p = 1023; brs[tid] = g_br[n * 1024 + p]; }
        __syncthreads();

        float s[4][4];
#pragma unroll
        for (int i = 0; i < 4; i++)
#pragma unroll
            for (int j = 0; j < 4; j++) s[i][j] = 0.f;

        for (int d = 0; d < 64; ++d) {
            float qv[4], kv[4], rv[7];
#pragma unroll
            for (int i = 0; i < 4; i++) qv[i] = Qs[(ty * 4 + i) * 65 + d];
#pragma unroll
            for (int j = 0; j < 4; j++) kv[j] = Ks[(tx * 4 + j) * 65 + d];
#pragma unroll
            for (int u = 0; u < 7; u++) rv[u] = RKs[(tbase - 3 + u) * 65 + d];
#pragma unroll
            for (int i = 0; i < 4; i++)
#pragma unroll
                for (int j = 0; j < 4; j++) {
                    s[i][j] = fmaf(qv[i], kv[j], s[i][j]);
                    s[i][j] = fmaf(qv[i], rv[j - i + 3], s[i][j]);
                }
        }
        // bias + scale + causal mask
#pragma unroll
        for (int i = 0; i < 4; i++) {
            int gi = i0 + ty * 4 + i;
#pragma unroll
            for (int j = 0; j < 4; j++) {
                int gj = j0 + tx * 4 + j;
                float v = (s[i][j] + bks[tx * 4 + j] + brs[tbase + j - i]) * 0.125f;
                s[i][j] = (gj > gi) ? -1e30f : v;
            }
        }
        // online softmax (row groups = 16 lanes sharing ty)
#pragma unroll
        for (int i = 0; i < 4; i++) {
            float rmax = fmaxf(fmaxf(s[i][0], s[i][1]), fmaxf(s[i][2], s[i][3]));
#pragma unroll
            for (int o = 8; o >= 1; o >>= 1) rmax = fmaxf(rmax, __shfl_xor_sync(0xffffffffu, rmax, o));
            float mnew = fmaxf(m[i], rmax);
            float fac = __expf(m[i] - mnew);
            float rsum = 0.f;
#pragma unroll
            for (int j = 0; j < 4; j++) {
                float p = __expf(s[i][j] - mnew);
                s[i][j] = p; rsum += p;
            }
#pragma unroll
            for (int o = 8; o >= 1; o >>= 1) rsum += __shfl_xor_sync(0xffffffffu, rsum, o);
            l[i] = l[i] * fac + rsum;
            m[i] = mnew;
#pragma unroll
            for (int j = 0; j < 4; j++) acc[i][j] *= fac;
#pragma unroll
            for (int j = 0; j < 4; j++) Ps[(ty * 4 + i) * 65 + tx * 4 + j] = s[i][j];
        }
        __syncthreads();
        // O += P @ V  (dhead columns tx*4..tx*4+3)
        for (int jj = 0; jj < 64; ++jj) {
            float pv[4], vv[4];
#pragma unroll
            for (int i = 0; i < 4; i++) pv[i] = Ps[(ty * 4 + i) * 65 + jj];
#pragma unroll
            for (int j = 0; j < 4; j++) vv[j] = Vs[jj * 65 + tx * 4 + j];
#pragma unroll
            for (int i = 0; i < 4; i++)
#pragma unroll
                for (int j = 0; j < 4; j++) acc[i][j] = fmaf(pv[i], vv[j], acc[i][j]);
        }
    }
#pragma unroll
    for (int i = 0; i < 4; i++) {
        float inv = 1.f / l[i];
        int gi = i0 + ty * 4 + i;
#pragma unroll
        for (int j = 0; j < 4; j++)
            av[((size_t)gi * BSZ + b) * DMODEL + n * 64 + tx * 4 + j] = acc[i][j] * inv;
    }
}

// ---------------- residual + layernorm -------------------------------------
__global__ __launch_bounds__(128) void ln_kernel(
    const float* __restrict__ w, const float* __restrict__ g,
    const float* __restrict__ bta, float* __restrict__ out)
{
    int row = blockIdx.x;
    int tid = threadIdx.x;
    const float* wr = w + (size_t)row * DMODEL;
    const float* ar = g_ao + (size_t)row * DMODEL;
    float x[4]; float s = 0.f, s2 = 0.f;
#pragma unroll
    for (int u = 0; u < 4; u++) {
        int c = tid + u * 128;
        x[u] = wr[c] + ar[c];
        s += x[u]; s2 += x[u] * x[u];
    }
#pragma unroll
    for (int o = 16; o >= 1; o >>= 1) {
        s += __shfl_xor_sync(0xffffffffu, s, o);
        s2 += __shfl_xor_sync(0xffffffffu, s2, o);
    }
    __shared__ float ss[4], ss2[4];
    int wid = tid >> 5, lane = tid & 31;
    if (lane == 0) { ss[wid] = s; ss2[wid] = s2; }
    __syncthreads();
    s = ss[0] + ss[1] + ss[2] + ss[3];
    s2 = ss2[0] + ss2[1] + ss2[2] + ss2[3];
    float mu = s * (1.f / 512.f);
    float var = s2 * (1.f / 512.f) - mu * mu;
    float rstd = rsqrtf(var + 1e-5f);
#pragma unroll
    for (int u = 0; u < 4; u++) {
        int c = tid + u * 128;
        out[(size_t)row * DMODEL + c] = (x[u] - mu) * rstd * g[c] + bta[c];
    }
}

// ---------------- launch ----------------------------------------------------
extern "C" void kernel_launch(void* const* d_in, const int* in_sizes, int n_in,
                              void* d_out, int out_size)
{
    const float* w    = (const float*)d_in[0];
    const float* r    = (const float*)d_in[1];
    const float* rwb  = (const float*)d_in[2];
    const float* rrb  = (const float*)d_in[3];
    // d_in[4] = attn_mask (ignored; causal mask is computed analytically)
    const float* Wqkv = (const float*)d_in[5];
    const float* Wr   = (const float*)d_in[6];
    const float* Wo   = (const float*)d_in[7];
    const float* lng  = (const float*)d_in[8];
    const float* lnb  = (const float*)d_in[9];
    float* out = (float*)d_out;

    float *wheads, *rk, *av, *ao;
    cudaGetSymbolAddress((void**)&wheads, g_wheads);
    cudaGetSymbolAddress((void**)&rk, g_rk);
    cudaGetSymbolAddress((void**)&av, g_av);
    cudaGetSymbolAddress((void**)&ao, g_ao);

    const int ATTN_SMEM = (64 * 65 * 4 + 128 * 65 + 64 + 128) * (int)sizeof(float);
    cudaFuncSetAttribute(attn_kernel, cudaFuncAttributeMaxDynamicSharedMemorySize, ATTN_SMEM);

    // 1) w_heads = w @ W_qkv : [8192,512] x [512,1536]
    sgemm_k<<<dim3(1536 / 64, 8192 / 64), 256>>>(w, DMODEL, Wqkv, 3 * DMODEL, wheads, 3 * DMODEL, DMODEL);
    // 2) r_head_k = r[:,0,:] @ W_r : [1024,512] x [512,512]  (row stride BSZ*DMODEL)
    sgemm_k<<<dim3(512 / 64, 1024 / 64), 256>>>(r, BSZ * DMODEL, Wr, DMODEL, rk, DMODEL, DMODEL);
    // 3) rank-1 bias terms
    biask_kernel<<<BSZ * NHEAD * QLEN / 8, 256>>>(rwb);
    biasr_kernel<<<NHEAD * QLEN / 8, 256>>>(rrb);
    // 4) fused causal attention with rel-shift
    attn_kernel<<<dim3(QLEN / 64, BSZ * NHEAD), 256, ATTN_SMEM>>>(av);
    // 5) attn_out = attn_vec @ W_o : [8192,512] x [512,512]
    sgemm_k<<<dim3(512 / 64, 8192 / 64), 256>>>(av, DMODEL, Wo, DMODEL, ao, DMODEL, DMODEL);
    // 6) layernorm(w + attn_out)
    ln_kernel<<<QLEN * BSZ, 128>>>(w, lng, lnb, out);
}

// round 3
// speedup vs baseline: 1.2984x; 1.2984x over previous
#include <cuda_runtime.h>
#include <cstdint>
#include <cstddef>

#define QLEN 1024
#define BSZ 8
#define DMODEL 512
#define NHEAD 8
#define DHEAD 64

// ---------------- scratch (device globals: allocation-free) ----------------
__device__ float g_wheads[QLEN * BSZ * 3 * DMODEL]; // [q][b][1536]  q|k|v each n*64+d
__device__ float g_rk[QLEN * DMODEL];               // [p][n*64+d]
__device__ float g_bk[BSZ * NHEAD * QLEN];          // [(b*8+n)][j] = rwb_n . k_jbn
__device__ float g_br[NHEAD * QLEN];                // [n][p]       = rrb_n . rk_pn
__device__ float g_av[QLEN * BSZ * DMODEL];         // attn_vec [q][b][n*64+d]
__device__ float g_ao[QLEN * BSZ * DMODEL];         // attn_out

// ---------------- tf32 helpers ---------------------------------------------
__device__ __forceinline__ float to_tf32(float x) {
    uint32_t r;
    asm("cvt.rna.tf32.f32 %0, %1;" : "=r"(r) : "f"(x));
    return __uint_as_float(r);
}

__device__ __forceinline__ void mma_tf32(float* c, const uint32_t* a, const uint32_t* b) {
    asm volatile(
        "mma.sync.aligned.m16n8k8.row.col.f32.tf32.tf32.f32 "
        "{%0,%1,%2,%3}, {%4,%5,%6,%7}, {%8,%9}, {%0,%1,%2,%3};"
        : "+f"(c[0]), "+f"(c[1]), "+f"(c[2]), "+f"(c[3])
        : "r"(a[0]), "r"(a[1]), "r"(a[2]), "r"(a[3]), "r"(b[0]), "r"(b[1]));
}

// ---------------- tf32 tensor-core GEMM: C[M,N] = A[M,K] * B[K,N] ----------
// 128x128 tile, BK=32, 256 threads (8 warps: 2m x 4n), warp tile 64x32.
// M,N multiples of 128; K multiple of 32.
__global__ __launch_bounds__(256) void gemm_tf32(
    const float* __restrict__ A, int lda,
    const float* __restrict__ B, int ldb,
    float* __restrict__ C, int ldc, int K)
{
    __shared__ float As[128][36];   // [m][k], stride 36 -> bank (4m+k)%32, frag loads conflict-free
    __shared__ float Bs[32][136];   // [k][n], stride 136 -> bank (8k+n)%32, frag loads conflict-free

    const int tid = threadIdx.x;
    const int m0 = blockIdx.y * 128, n0 = blockIdx.x * 128;
    const int warp = tid >> 5, lane = tid & 31;
    const int g = lane >> 2, tig = lane & 3;
    const int wm = (warp & 1) * 64;
    const int wn = (warp >> 1) * 32;

    float acc[4][4][4];
#pragma unroll
    for (int mf = 0; mf < 4; mf++)
#pragma unroll
        for (int nf = 0; nf < 4; nf++)
#pragma unroll
            for (int r = 0; r < 4; r++) acc[mf][nf][r] = 0.f;

    // global-load register staging
    float4 ra[4], rb[4];
#pragma unroll
    for (int i = 0; i < 4; i++) {
        int idx = tid + i * 256;
        int am = idx >> 3, akq = (idx & 7) << 2;          // A tile: 128 x 32
        ra[i] = *(const float4*)&A[(size_t)(m0 + am) * lda + akq];
        int bk = idx >> 5, bn4 = (idx & 31) << 2;         // B tile: 32 x 128
        rb[i] = *(const float4*)&B[(size_t)bk * ldb + n0 + bn4];
    }

    for (int k0 = 0; k0 < K; k0 += 32) {
        __syncthreads();
#pragma unroll
        for (int i = 0; i < 4; i++) {
            int idx = tid + i * 256;
            int am = idx >> 3, akq = (idx & 7) << 2;
            As[am][akq + 0] = to_tf32(ra[i].x);
            As[am][akq + 1] = to_tf32(ra[i].y);
            As[am][akq + 2] = to_tf32(ra[i].z);
            As[am][akq + 3] = to_tf32(ra[i].w);
            int bk = idx >> 5, bn4 = (idx & 31) << 2;
            Bs[bk][bn4 + 0] = to_tf32(rb[i].x);
            Bs[bk][bn4 + 1] = to_tf32(rb[i].y);
            Bs[bk][bn4 + 2] = to_tf32(rb[i].z);
            Bs[bk][bn4 + 3] = to_tf32(rb[i].w);
        }
        __syncthreads();
        if (k0 + 32 < K) {
#pragma unroll
            for (int i = 0; i < 4; i++) {
                int idx = tid + i * 256;
                int am = idx >> 3, akq = (idx & 7) << 2;
                ra[i] = *(const float4*)&A[(size_t)(m0 + am) * lda + k0 + 32 + akq];
                int bk = idx >> 5, bn4 = (idx & 31) << 2;
                rb[i] = *(const float4*)&B[(size_t)(k0 + 32 + bk) * ldb + n0 + bn4];
            }
        }
#pragma unroll
        for (int ks = 0; ks < 4; ++ks) {
            const int kk = ks * 8;
            uint32_t af[4][4], bf[4][2];
#pragma unroll
            for (int mf = 0; mf < 4; mf++) {
                int m = wm + mf * 16 + g;
                af[mf][0] = __float_as_uint(As[m][kk + tig]);
                af[mf][1] = __float_as_uint(As[m + 8][kk + tig]);
                af[mf][2] = __float_as_uint(As[m][kk + tig + 4]);
                af[mf][3] = __float_as_uint(As[m + 8][kk + tig + 4]);
            }
#pragma unroll
            for (int nf = 0; nf < 4; nf++) {
                int n = wn + nf * 8 + g;
                bf[nf][0] = __float_as_uint(Bs[kk + tig][n]);
                bf[nf][1] = __float_as_uint(Bs[kk + tig + 4][n]);
            }
#pragma unroll
            for (int mf = 0; mf < 4; mf++)
#pragma unroll
                for (int nf = 0; nf < 4; nf++) mma_tf32(acc[mf][nf], af[mf], bf[nf]);
        }
    }

#pragma unroll
    for (int mf = 0; mf < 4; mf++) {
        int m = m0 + wm + mf * 16 + g;
#pragma unroll
        for (int nf = 0; nf < 4; nf++) {
            int n = n0 + wn + nf * 8 + tig * 2;
            float2 v0 = make_float2(acc[mf][nf][0], acc[mf][nf][1]);
            float2 v1 = make_float2(acc[mf][nf][2], acc[mf][nf][3]);
            *(float2*)&C[(size_t)m * ldc + n] = v0;
            *(float2*)&C[(size_t)(m + 8) * ldc + n] = v1;
        }
    }
}

// ---------------- bias precompute: bk[b][n][j] = rwb_n . K_jbn -------------
__global__ __launch_bounds__(256) void biask_kernel(const float* __restrict__ rwb)
{
    int id = blockIdx.x * 8 + (threadIdx.x >> 5);
    int lane = threadIdx.x & 31;
    int j = id & 1023;
    int bn = id >> 10;
    int b = bn >> 3, n = bn & 7;
    const float* base = g_wheads + ((size_t)j * BSZ + b) * 1536 + 512 + n * 64;
    const float* wv = rwb + n * 64;
    float v = wv[lane] * base[lane] + wv[lane + 32] * base[lane + 32];
#pragma unroll
    for (int o = 16; o >= 1; o >>= 1) v += __shfl_xor_sync(0xffffffffu, v, o);
    if (lane == 0) g_bk[id] = v;
}

__global__ __launch_bounds__(256) void biasr_kernel(const float* __restrict__ rrb)
{
    int id = blockIdx.x * 8 + (threadIdx.x >> 5);
    int lane = threadIdx.x & 31;
    int p = id & 1023;
    int n = id >> 10;
    const float* base = g_rk + (size_t)p * DMODEL + n * 64;
    const float* wv = rrb + n * 64;
    float v = wv[lane] * base[lane] + wv[lane + 32] * base[lane + 32];
#pragma unroll
    for (int o = 16; o >= 1; o >>= 1) v += __shfl_xor_sync(0xffffffffu, v, o);
    if (lane == 0) g_br[id] = v;
}

// ---------------- fused causal attention with rel-shift --------------------
__global__ __launch_bounds__(256) void attn_kernel(float* __restrict__ av)
{
    extern __shared__ float smf[];
    float* Qs  = smf;             // 64*65
    float* Ks  = Qs + 64 * 65;
    float* Vs  = Ks + 64 * 65;
    float* RKs = Vs + 64 * 65;    // 128*65
    float* Ps  = RKs + 128 * 65;  // 64*65
    float* bks = Ps + 64 * 65;    // 64
    float* brs = bks + 64;        // 128

    const int i0 = (gridDim.x - 1 - blockIdx.x) * 64;   // heavy tiles first
    const int bn = blockIdx.y;
    const int b = bn >> 3, n = bn & 7;
    const int tid = threadIdx.x;
    const int ty = tid >> 4, tx = tid & 15;
    const int tbase = 63 + 4 * (tx - ty);

    for (int idx = tid; idx < 64 * 16; idx += 256) {
        int r = idx >> 4, q4 = (idx & 15) << 2;
        float4 v = *(const float4*)(g_wheads + ((size_t)(i0 + r) * BSZ + b) * 1536 + n * 64 + q4);
        float* dst = Qs + r * 65 + q4;
        dst[0] = v.x; dst[1] = v.y; dst[2] = v.z; dst[3] = v.w;
    }

    float m[4], l[4], acc[4][4];
#pragma unroll
    for (int i = 0; i < 4; i++) {
        m[i] = -1e30f; l[i] = 0.f;
#pragma unroll
        for (int j = 0; j < 4; j++) acc[i][j] = 0.f;
    }

    const int ntiles = i0 / 64 + 1;
    for (int jt = 0; jt < ntiles; ++jt) {
        const int j0 = jt * 64;
        const int pmin = (QLEN - 64) - i0 + j0;
        __syncthreads();
        for (int idx = tid; idx < 64 * 16; idx += 256) {
            int r = idx >> 4, q4 = (idx & 15) << 2;
            const float* srcK = g_wheads + ((size_t)(j0 + r) * BSZ + b) * 1536 + 512 + n * 64 + q4;
            float4 k4 = *(const float4*)srcK;
            float4 v4 = *(const float4*)(srcK + 512);
            float* dK = Ks + r * 65 + q4;
            dK[0] = k4.x; dK[1] = k4.y; dK[2] = k4.z; dK[3] = k4.w;
            float* dV = Vs + r * 65 + q4;
            dV[0] = v4.x; dV[1] = v4.y; dV[2] = v4.z; dV[3] = v4.w;
        }
        for (int idx = tid; idx < 128 * 16; idx += 256) {
            int t = idx >> 4, q4 = (idx & 15) << 2;
            int p = pmin + t; if (p > QLEN - 1) p = QLEN - 1;
            float4 v = *(const float4*)(g_rk + (size_t)p * DMODEL + n * 64 + q4);
            float* dst = RKs + t * 65 + q4;
            dst[0] = v.x; dst[1] = v.y; dst[2] = v.z; dst[3] = v.w;
        }
        if (tid < 64) bks[tid] = g_bk[((size_t)b * 8 + n) * 1024 + j0 + tid];
        if (tid < 128) { int p = pmin + tid; if (p > 1023) p = 1023; brs[tid] = g_br[n * 1024 + p]; }
        __syncthreads();

        float s[4][4];
#pragma unroll
        for (int i = 0; i < 4; i++)
#pragma unroll
            for (int j = 0; j < 4; j++) s[i][j] = 0.f;

        for (int d = 0; d < 64; ++d) {
            float qv[4], kv[4], rv[7];
#pragma unroll
            for (int i = 0; i < 4; i++) qv[i] = Qs[(ty * 4 + i) * 65 + d];
#pragma unroll
            for (int j = 0; j < 4; j++) kv[j] = Ks[(tx * 4 + j) * 65 + d];
#pragma unroll
            for (int u = 0; u < 7; u++) rv[u] = RKs[(tbase - 3 + u) * 65 + d];
#pragma unroll
            for (int i = 0; i < 4; i++)
#pragma unroll
                for (int j = 0; j < 4; j++) {
                    s[i][j] = fmaf(qv[i], kv[j], s[i][j]);
                    s[i][j] = fmaf(qv[i], rv[j - i + 3], s[i][j]);
                }
        }
#pragma unroll
        for (int i = 0; i < 4; i++) {
            int gi = i0 + ty * 4 + i;
#pragma unroll
            for (int j = 0; j < 4; j++) {
                int gj = j0 + tx * 4 + j;
                float v = (s[i][j] + bks[tx * 4 + j] + brs[tbase + j - i]) * 0.125f;
                s[i][j] = (gj > gi) ? -1e30f : v;
            }
        }
#pragma unroll
        for (int i = 0; i < 4; i++) {
            float rmax = fmaxf(fmaxf(s[i][0], s[i][1]), fmaxf(s[i][2], s[i][3]));
#pragma unroll
            for (int o = 8; o >= 1; o >>= 1) rmax = fmaxf(rmax, __shfl_xor_sync(0xffffffffu, rmax, o));
            float mnew = fmaxf(m[i], rmax);
            float fac = __expf(m[i] - mnew);
            float rsum = 0.f;
#pragma unroll
            for (int j = 0; j < 4; j++) {
                float p = __expf(s[i][j] - mnew);
                s[i][j] = p; rsum += p;
            }
#pragma unroll
            for (int o = 8; o >= 1; o >>= 1) rsum += __shfl_xor_sync(0xffffffffu, rsum, o);
            l[i] = l[i] * fac + rsum;
            m[i] = mnew;
#pragma unroll
            for (int j = 0; j < 4; j++) acc[i][j] *= fac;
#pragma unroll
            for (int j = 0; j < 4; j++) Ps[(ty * 4 + i) * 65 + tx * 4 + j] = s[i][j];
        }
        __syncthreads();
        for (int jj = 0; jj < 64; ++jj) {
            float pv[4], vv[4];
#pragma unroll
            for (int i = 0; i < 4; i++) pv[i] = Ps[(ty * 4 + i) * 65 + jj];
#pragma unroll
            for (int j = 0; j < 4; j++) vv[j] = Vs[jj * 65 + tx * 4 + j];
#pragma unroll
            for (int i = 0; i < 4; i++)
#pragma unroll
                for (int j = 0; j < 4; j++) acc[i][j] = fmaf(pv[i], vv[j], acc[i][j]);
        }
    }
#pragma unroll
    for (int i = 0; i < 4; i++) {
        float inv = 1.f / l[i];
        int gi = i0 + ty * 4 + i;
#pragma unroll
        for (int j = 0; j < 4; j++)
            av[((size_t)gi * BSZ + b) * DMODEL + n * 64 + tx * 4 + j] = acc[i][j] * inv;
    }
}

// ---------------- residual + layernorm -------------------------------------
__global__ __launch_bounds__(128) void ln_kernel(
    const float* __restrict__ w, const float* __restrict__ g,
    const float* __restrict__ bta, float* __restrict__ out)
{
    int row = blockIdx.x;
    int tid = threadIdx.x;
    const float* wr = w + (size_t)row * DMODEL;
    const float* ar = g_ao + (size_t)row * DMODEL;
    float x[4]; float s = 0.f, s2 = 0.f;
#pragma unroll
    for (int u = 0; u < 4; u++) {
        int c = tid + u * 128;
        x[u] = wr[c] + ar[c];
        s += x[u]; s2 += x[u] * x[u];
    }
#pragma unroll
    for (int o = 16; o >= 1; o >>= 1) {
        s += __shfl_xor_sync(0xffffffffu, s, o);
        s2 += __shfl_xor_sync(0xffffffffu, s2, o);
    }
    __shared__ float ss[4], ss2[4];
    int wid = tid >> 5, lane = tid & 31;
    if (lane == 0) { ss[wid] = s; ss2[wid] = s2; }
    __syncthreads();
    s = ss[0] + ss[1] + ss[2] + ss[3];
    s2 = ss2[0] + ss2[1] + ss2[2] + ss2[3];
    float mu = s * (1.f / 512.f);
    float var = s2 * (1.f / 512.f) - mu * mu;
    float rstd = rsqrtf(var + 1e-5f);
#pragma unroll
    for (int u = 0; u < 4; u++) {
        int c = tid + u * 128;
        out[(size_t)row * DMODEL + c] = (x[u] - mu) * rstd * g[c] + bta[c];
    }
}

// ---------------- launch ----------------------------------------------------
extern "C" void kernel_launch(void* const* d_in, const int* in_sizes, int n_in,
                              void* d_out, int out_size)
{
    const float* w    = (const float*)d_in[0];
    const float* r    = (const float*)d_in[1];
    const float* rwb  = (const float*)d_in[2];
    const float* rrb  = (const float*)d_in[3];
    // d_in[4] = attn_mask (causal mask computed analytically)
    const float* Wqkv = (const float*)d_in[5];
    const float* Wr   = (const float*)d_in[6];
    const float* Wo   = (const float*)d_in[7];
    const float* lng  = (const float*)d_in[8];
    const float* lnb  = (const float*)d_in[9];
    float* out = (float*)d_out;

    float *wheads, *rk, *av, *ao;
    cudaGetSymbolAddress((void**)&wheads, g_wheads);
    cudaGetSymbolAddress((void**)&rk, g_rk);
    cudaGetSymbolAddress((void**)&av, g_av);
    cudaGetSymbolAddress((void**)&ao, g_ao);

    const int ATTN_SMEM = (64 * 65 * 4 + 128 * 65 + 64 + 128) * (int)sizeof(float);
    cudaFuncSetAttribute(attn_kernel, cudaFuncAttributeMaxDynamicSharedMemorySize, ATTN_SMEM);

    // 1) w_heads = w @ W_qkv : [8192,512] x [512,1536]   (tf32 tensor cores)
    gemm_tf32<<<dim3(1536 / 128, 8192 / 128), 256>>>(w, DMODEL, Wqkv, 3 * DMODEL, wheads, 3 * DMODEL, DMODEL);
    // 2) r_head_k = r[:,0,:] @ W_r : [1024,512] x [512,512]  (row stride BSZ*DMODEL)
    gemm_tf32<<<dim3(512 / 128, 1024 / 128), 256>>>(r, BSZ * DMODEL, Wr, DMODEL, rk, DMODEL, DMODEL);
    // 3) rank-1 bias terms
    biask_kernel<<<BSZ * NHEAD * QLEN / 8, 256>>>(rwb);
    biasr_kernel<<<NHEAD * QLEN / 8, 256>>>(rrb);
    // 4) fused causal attention with rel-shift
    attn_kernel<<<dim3(QLEN / 64, BSZ * NHEAD), 256, ATTN_SMEM>>>(av);
    // 5) attn_out = attn_vec @ W_o : [8192,512] x [512,512]
    gemm_tf32<<<dim3(512 / 128, 8192 / 128), 256>>>(av, DMODEL, Wo, DMODEL, ao, DMODEL, DMODEL);
    // 6) layernorm(w + attn_out)
    ln_kernel<<<QLEN * BSZ, 128>>>(w, lng, lnb, out);
}

// round 4
// speedup vs baseline: 2.3416x; 1.8035x over previous
#include <cuda_runtime.h>
#include <cstdint>
#include <cstddef>

#define QLEN 1024
#define BSZ 8
#define DMODEL 512
#define NHEAD 8
#define DHEAD 64

// ---------------- scratch (device globals: allocation-free) ----------------
__device__ float g_wheads[QLEN * BSZ * 3 * DMODEL]; // [q][b][1536]  q|k|v each n*64+d
__device__ float g_rk[QLEN * DMODEL];               // [p][n*64+d]
__device__ float g_bk[BSZ * NHEAD * QLEN];          // [(b*8+n)][j] = rwb_n . k_jbn
__device__ float g_br[NHEAD * QLEN];                // [n][p]       = rrb_n . rk_pn
__device__ float g_av[QLEN * BSZ * DMODEL];         // attn_vec [q][b][n*64+d]
__device__ float g_ao[QLEN * BSZ * DMODEL];         // attn_out

// ---------------- tf32 helpers ---------------------------------------------
__device__ __forceinline__ float to_tf32(float x) {
    uint32_t r;
    asm("cvt.rna.tf32.f32 %0, %1;" : "=r"(r) : "f"(x));
    return __uint_as_float(r);
}

__device__ __forceinline__ void mma_tf32(float* c, const uint32_t* a, const uint32_t* b) {
    asm volatile(
        "mma.sync.aligned.m16n8k8.row.col.f32.tf32.tf32.f32 "
        "{%0,%1,%2,%3}, {%4,%5,%6,%7}, {%8,%9}, {%0,%1,%2,%3};"
        : "+f"(c[0]), "+f"(c[1]), "+f"(c[2]), "+f"(c[3])
        : "r"(a[0]), "r"(a[1]), "r"(a[2]), "r"(a[3]), "r"(b[0]), "r"(b[1]));
}

// ---------------- tf32 tensor-core GEMM: C[M,N] = A[M,K] * B[K,N] ----------
__global__ __launch_bounds__(256) void gemm_tf32(
    const float* __restrict__ A, int lda,
    const float* __restrict__ B, int ldb,
    float* __restrict__ C, int ldc, int K)
{
    __shared__ float As[128][36];
    __shared__ float Bs[32][136];

    const int tid = threadIdx.x;
    const int m0 = blockIdx.y * 128, n0 = blockIdx.x * 128;
    const int warp = tid >> 5, lane = tid & 31;
    const int g = lane >> 2, tig = lane & 3;
    const int wm = (warp & 1) * 64;
    const int wn = (warp >> 1) * 32;

    float acc[4][4][4];
#pragma unroll
    for (int mf = 0; mf < 4; mf++)
#pragma unroll
        for (int nf = 0; nf < 4; nf++)
#pragma unroll
            for (int r = 0; r < 4; r++) acc[mf][nf][r] = 0.f;

    float4 ra[4], rb[4];
#pragma unroll
    for (int i = 0; i < 4; i++) {
        int idx = tid + i * 256;
        int am = idx >> 3, akq = (idx & 7) << 2;
        ra[i] = *(const float4*)&A[(size_t)(m0 + am) * lda + akq];
        int bk = idx >> 5, bn4 = (idx & 31) << 2;
        rb[i] = *(const float4*)&B[(size_t)bk * ldb + n0 + bn4];
    }

    for (int k0 = 0; k0 < K; k0 += 32) {
        __syncthreads();
#pragma unroll
        for (int i = 0; i < 4; i++) {
            int idx = tid + i * 256;
            int am = idx >> 3, akq = (idx & 7) << 2;
            As[am][akq + 0] = to_tf32(ra[i].x);
            As[am][akq + 1] = to_tf32(ra[i].y);
            As[am][akq + 2] = to_tf32(ra[i].z);
            As[am][akq + 3] = to_tf32(ra[i].w);
            int bk = idx >> 5, bn4 = (idx & 31) << 2;
            Bs[bk][bn4 + 0] = to_tf32(rb[i].x);
            Bs[bk][bn4 + 1] = to_tf32(rb[i].y);
            Bs[bk][bn4 + 2] = to_tf32(rb[i].z);
            Bs[bk][bn4 + 3] = to_tf32(rb[i].w);
        }
        __syncthreads();
        if (k0 + 32 < K) {
#pragma unroll
            for (int i = 0; i < 4; i++) {
                int idx = tid + i * 256;
                int am = idx >> 3, akq = (idx & 7) << 2;
                ra[i] = *(const float4*)&A[(size_t)(m0 + am) * lda + k0 + 32 + akq];
                int bk = idx >> 5, bn4 = (idx & 31) << 2;
                rb[i] = *(const float4*)&B[(size_t)(k0 + 32 + bk) * ldb + n0 + bn4];
            }
        }
#pragma unroll
        for (int ks = 0; ks < 4; ++ks) {
            const int kk = ks * 8;
            uint32_t af[4][4], bf[4][2];
#pragma unroll
            for (int mf = 0; mf < 4; mf++) {
                int m = wm + mf * 16 + g;
                af[mf][0] = __float_as_uint(As[m][kk + tig]);
                af[mf][1] = __float_as_uint(As[m + 8][kk + tig]);
                af[mf][2] = __float_as_uint(As[m][kk + tig + 4]);
                af[mf][3] = __float_as_uint(As[m + 8][kk + tig + 4]);
            }
#pragma unroll
            for (int nf = 0; nf < 4; nf++) {
                int n = wn + nf * 8 + g;
                bf[nf][0] = __float_as_uint(Bs[kk + tig][n]);
                bf[nf][1] = __float_as_uint(Bs[kk + tig + 4][n]);
            }
#pragma unroll
            for (int mf = 0; mf < 4; mf++)
#pragma unroll
                for (int nf = 0; nf < 4; nf++) mma_tf32(acc[mf][nf], af[mf], bf[nf]);
        }
    }

#pragma unroll
    for (int mf = 0; mf < 4; mf++) {
        int m = m0 + wm + mf * 16 + g;
#pragma unroll
        for (int nf = 0; nf < 4; nf++) {
            int n = n0 + wn + nf * 8 + tig * 2;
            float2 v0 = make_float2(acc[mf][nf][0], acc[mf][nf][1]);
            float2 v1 = make_float2(acc[mf][nf][2], acc[mf][nf][3]);
            *(float2*)&C[(size_t)m * ldc + n] = v0;
            *(float2*)&C[(size_t)(m + 8) * ldc + n] = v1;
        }
    }
}

// ---------------- bias precompute -------------------------------------------
__global__ __launch_bounds__(256) void biask_kernel(const float* __restrict__ rwb)
{
    int id = blockIdx.x * 8 + (threadIdx.x >> 5);
    int lane = threadIdx.x & 31;
    int j = id & 1023;
    int bn = id >> 10;
    int b = bn >> 3, n = bn & 7;
    const float* base = g_wheads + ((size_t)j * BSZ + b) * 1536 + 512 + n * 64;
    const float* wv = rwb + n * 64;
    float v = wv[lane] * base[lane] + wv[lane + 32] * base[lane + 32];
#pragma unroll
    for (int o = 16; o >= 1; o >>= 1) v += __shfl_xor_sync(0xffffffffu, v, o);
    if (lane == 0) g_bk[id] = v;
}

__global__ __launch_bounds__(256) void biasr_kernel(const float* __restrict__ rrb)
{
    int id = blockIdx.x * 8 + (threadIdx.x >> 5);
    int lane = threadIdx.x & 31;
    int p = id & 1023;
    int n = id >> 10;
    const float* base = g_rk + (size_t)p * DMODEL + n * 64;
    const float* wv = rrb + n * 64;
    float v = wv[lane] * base[lane] + wv[lane + 32] * base[lane + 32];
#pragma unroll
    for (int o = 16; o >= 1; o >>= 1) v += __shfl_xor_sync(0xffffffffu, v, o);
    if (lane == 0) g_br[id] = v;
}

// ---------------- tensor-core fused causal attention with rel-shift --------
// SMEM float offsets
#define A_QS   0
#define A_KS   4352            // Qs 64*68
#define A_VS   8704            // Ks 64*68
#define A_RKS  13312           // Vs 64*72
#define A_ES   22016           // RKs 128*68
#define A_SS   30464           // Es 64*132  (Ss=Ps alias, 64*68)
#define A_BKS  34816
#define A_BRS  34880
#define A_FAC  35008
#define A_LINV 35072
#define A_TOT  35136

__global__ __launch_bounds__(256) void attn_mma_kernel(float* __restrict__ av)
{
    extern __shared__ float smf[];
    float* Qs  = smf + A_QS;    // [64][68] tf32
    float* Ks  = smf + A_KS;    // [64][68] tf32
    float* Vs  = smf + A_VS;    // [64][72] tf32
    float* RKs = smf + A_RKS;   // [128][68] tf32
    float* Es  = smf + A_ES;    // [64][132] fp32 accum
    float* Ss  = smf + A_SS;    // [64][68]  fp32 accum / P (tf32) alias
    float* bks = smf + A_BKS;   // [64]
    float* brs = smf + A_BRS;   // [128]
    float* fac = smf + A_FAC;   // [64]
    float* linv= smf + A_LINV;  // [64]

    const int i0 = (gridDim.x - 1 - blockIdx.x) * 64;   // heavy tiles first
    const int bn = blockIdx.y;
    const int b = bn >> 3, n = bn & 7;
    const int tid = threadIdx.x;

    // mma thread ids
    const int warp = tid >> 5, lane = tid & 31;
    const int g = lane >> 2, tig = lane & 3;
    const int wm = (warp & 3) * 16;          // 4 row-groups of 16
    const int wn = (warp >> 2) * 32;         // 2 col-groups of 32 (AC/PV)
    const int wne = (warp >> 2) * 64;        // 2 col-groups of 64 (E)

    // softmax thread ids (16x16, 4x4 microtile)
    const int ty = tid >> 4, tx = tid & 15;
    const int tbase = 63 + 4 * (tx - ty);    // t(i,j) = tbase + j - i, in [0,126]

    // ---- load Q tile (tf32) ----
    for (int idx = tid; idx < 64 * 16; idx += 256) {
        int r = idx >> 4, q4 = (idx & 15) << 2;
        float4 v = *(const float4*)(g_wheads + ((size_t)(i0 + r) * BSZ + b) * 1536 + n * 64 + q4);
        float* dst = Qs + r * 68 + q4;
        dst[0] = to_tf32(v.x); dst[1] = to_tf32(v.y);
        dst[2] = to_tf32(v.z); dst[3] = to_tf32(v.w);
    }

    // softmax state (softmax layout) + O accum (mma layout)
    float m[4], l[4];
#pragma unroll
    for (int i = 0; i < 4; i++) { m[i] = -1e30f; l[i] = 0.f; }
    float accO[4][4];
#pragma unroll
    for (int nf = 0; nf < 4; nf++)
#pragma unroll
        for (int r = 0; r < 4; r++) accO[nf][r] = 0.f;

    const int ntiles = i0 / 64 + 1;
    for (int jt = 0; jt < ntiles; ++jt) {
        const int j0 = jt * 64;
        const int pmin = (QLEN - 64) - i0 + j0;   // >= 0
        __syncthreads();   // prev-iter consumers done

        // ---- load K, V (tf32) ----
        for (int idx = tid; idx < 64 * 16; idx += 256) {
            int r = idx >> 4, q4 = (idx & 15) << 2;
            const float* srcK = g_wheads + ((size_t)(j0 + r) * BSZ + b) * 1536 + 512 + n * 64 + q4;
            float4 k4 = *(const float4*)srcK;
            float4 v4 = *(const float4*)(srcK + 512);
            float* dK = Ks + r * 68 + q4;
            dK[0] = to_tf32(k4.x); dK[1] = to_tf32(k4.y);
            dK[2] = to_tf32(k4.z); dK[3] = to_tf32(k4.w);
            float* dV = Vs + r * 72 + q4;
            dV[0] = to_tf32(v4.x); dV[1] = to_tf32(v4.y);
            dV[2] = to_tf32(v4.z); dV[3] = to_tf32(v4.w);
        }
        // ---- load RK slab rows t=0..127, p = pmin + t clamped ----
        for (int idx = tid; idx < 128 * 16; idx += 256) {
            int t = idx >> 4, q4 = (idx & 15) << 2;
            int p = pmin + t; if (p > QLEN - 1) p = QLEN - 1;
            float4 v = *(const float4*)(g_rk + (size_t)p * DMODEL + n * 64 + q4);
            float* dst = RKs + t * 68 + q4;
            dst[0] = to_tf32(v.x); dst[1] = to_tf32(v.y);
            dst[2] = to_tf32(v.z); dst[3] = to_tf32(v.w);
        }
        if (tid < 64) bks[tid] = g_bk[((size_t)b * 8 + n) * 1024 + j0 + tid];
        if (tid < 128) { int p = pmin + tid; if (p > 1023) p = 1023; brs[tid] = g_br[n * 1024 + p]; }
        __syncthreads();

        // ---- AC = Q @ K^T : 64x64, k=64 ----
        {
            float acc[4][4];
#pragma unroll
            for (int nf = 0; nf < 4; nf++)
#pragma unroll
                for (int r = 0; r < 4; r++) acc[nf][r] = 0.f;
#pragma unroll
            for (int kk = 0; kk < 64; kk += 8) {
                uint32_t af[4];
                af[0] = __float_as_uint(Qs[(wm + g) * 68 + kk + tig]);
                af[1] = __float_as_uint(Qs[(wm + g + 8) * 68 + kk + tig]);
                af[2] = __float_as_uint(Qs[(wm + g) * 68 + kk + tig + 4]);
                af[3] = __float_as_uint(Qs[(wm + g + 8) * 68 + kk + tig + 4]);
#pragma unroll
                for (int nf = 0; nf < 4; nf++) {
                    int nn = wn + nf * 8 + g;
                    uint32_t bf[2];
                    bf[0] = __float_as_uint(Ks[nn * 68 + kk + tig]);
                    bf[1] = __float_as_uint(Ks[nn * 68 + kk + tig + 4]);
                    mma_tf32(acc[nf], af, bf);
                }
            }
#pragma unroll
            for (int nf = 0; nf < 4; nf++) {
                int nn = wn + nf * 8 + tig * 2;
                *(float2*)&Ss[(wm + g) * 68 + nn]     = make_float2(acc[nf][0], acc[nf][1]);
                *(float2*)&Ss[(wm + g + 8) * 68 + nn] = make_float2(acc[nf][2], acc[nf][3]);
            }
        }
        // ---- E = Q @ RK^T : 64x128, k=64 ----
        {
            float acc[8][4];
#pragma unroll
            for (int nf = 0; nf < 8; nf++)
#pragma unroll
                for (int r = 0; r < 4; r++) acc[nf][r] = 0.f;
#pragma unroll
            for (int kk = 0; kk < 64; kk += 8) {
                uint32_t af[4];
                af[0] = __float_as_uint(Qs[(wm + g) * 68 + kk + tig]);
                af[1] = __float_as_uint(Qs[(wm + g + 8) * 68 + kk + tig]);
                af[2] = __float_as_uint(Qs[(wm + g) * 68 + kk + tig + 4]);
                af[3] = __float_as_uint(Qs[(wm + g + 8) * 68 + kk + tig + 4]);
#pragma unroll
                for (int nf = 0; nf < 8; nf++) {
                    int tt = wne + nf * 8 + g;
                    uint32_t bf[2];
                    bf[0] = __float_as_uint(RKs[tt * 68 + kk + tig]);
                    bf[1] = __float_as_uint(RKs[tt * 68 + kk + tig + 4]);
                    mma_tf32(acc[nf], af, bf);
                }
            }
#pragma unroll
            for (int nf = 0; nf < 8; nf++) {
                int tt = wne + nf * 8 + tig * 2;
                *(float2*)&Es[(wm + g) * 132 + tt]     = make_float2(acc[nf][0], acc[nf][1]);
                *(float2*)&Es[(wm + g + 8) * 132 + tt] = make_float2(acc[nf][2], acc[nf][3]);
            }
        }
        __syncthreads();

        // ---- softmax (16x16 layout), write P (tf32) into Ss alias + fac ----
        {
            float s[4][4];
#pragma unroll
            for (int i = 0; i < 4; i++) {
                int il = ty * 4 + i;
                float4 acf = *(float4*)&Ss[il * 68 + tx * 4];
                float sv[4] = {acf.x, acf.y, acf.z, acf.w};
                int gi = i0 + il;
#pragma unroll
                for (int j = 0; j < 4; j++) {
                    int t = tbase + j - i;
                    int gj = j0 + tx * 4 + j;
                    float v = (sv[j] + Es[il * 132 + t] + bks[tx * 4 + j] + brs[t]) * 0.125f;
                    s[i][j] = (gj > gi) ? -1e30f : v;
                }
            }
#pragma unroll
            for (int i = 0; i < 4; i++) {
                float rmax = fmaxf(fmaxf(s[i][0], s[i][1]), fmaxf(s[i][2], s[i][3]));
#pragma unroll
                for (int o = 8; o >= 1; o >>= 1) rmax = fmaxf(rmax, __shfl_xor_sync(0xffffffffu, rmax, o));
                float mnew = fmaxf(m[i], rmax);
                float fc = __expf(m[i] - mnew);
                float rsum = 0.f;
#pragma unroll
                for (int j = 0; j < 4; j++) {
                    float p = __expf(s[i][j] - mnew);
                    s[i][j] = p; rsum += p;
                }
#pragma unroll
                for (int o = 8; o >= 1; o >>= 1) rsum += __shfl_xor_sync(0xffffffffu, rsum, o);
                l[i] = l[i] * fc + rsum;
                m[i] = mnew;
                if (tx == 0) fac[ty * 4 + i] = fc;
                // write P (tf32) — same elements this thread just read
                float4 pw = make_float4(to_tf32(s[i][0]), to_tf32(s[i][1]),
                                        to_tf32(s[i][2]), to_tf32(s[i][3]));
                *(float4*)&Ss[(ty * 4 + i) * 68 + tx * 4] = pw;
            }
        }
        __syncthreads();

        // ---- rescale O accum, then O += P @ V ----
        {
            float f0 = fac[wm + g], f1 = fac[wm + g + 8];
#pragma unroll
            for (int nf = 0; nf < 4; nf++) {
                accO[nf][0] *= f0; accO[nf][1] *= f0;
                accO[nf][2] *= f1; accO[nf][3] *= f1;
            }
#pragma unroll
            for (int kk = 0; kk < 64; kk += 8) {
                uint32_t af[4];
                af[0] = __float_as_uint(Ss[(wm + g) * 68 + kk + tig]);
                af[1] = __float_as_uint(Ss[(wm + g + 8) * 68 + kk + tig]);
                af[2] = __float_as_uint(Ss[(wm + g) * 68 + kk + tig + 4]);
                af[3] = __float_as_uint(Ss[(wm + g + 8) * 68 + kk + tig + 4]);
#pragma unroll
                for (int nf = 0; nf < 4; nf++) {
                    int nn = wn + nf * 8 + g;
                    uint32_t bf[2];
                    bf[0] = __float_as_uint(Vs[(kk + tig) * 72 + nn]);
                    bf[1] = __float_as_uint(Vs[(kk + tig + 4) * 72 + nn]);
                    mma_tf32(accO[nf], af, bf);
                }
            }
        }
    }

    // ---- epilogue: divide by l, store ----
    if (tx == 0) {
#pragma unroll
        for (int i = 0; i < 4; i++) linv[ty * 4 + i] = 1.f / l[i];
    }
    __syncthreads();
    {
        float f0 = linv[wm + g], f1 = linv[wm + g + 8];
        int gi0 = i0 + wm + g;
        int gi1 = i0 + wm + g + 8;
#pragma unroll
        for (int nf = 0; nf < 4; nf++) {
            int nn = wn + nf * 8 + tig * 2;
            *(float2*)&av[((size_t)gi0 * BSZ + b) * DMODEL + n * 64 + nn] =
                make_float2(accO[nf][0] * f0, accO[nf][1] * f0);
            *(float2*)&av[((size_t)gi1 * BSZ + b) * DMODEL + n * 64 + nn] =
                make_float2(accO[nf][2] * f1, accO[nf][3] * f1);
        }
    }
}

// ---------------- residual + layernorm -------------------------------------
__global__ __launch_bounds__(128) void ln_kernel(
    const float* __restrict__ w, const float* __restrict__ g,
    const float* __restrict__ bta, float* __restrict__ out)
{
    int row = blockIdx.x;
    int tid = threadIdx.x;
    const float* wr = w + (size_t)row * DMODEL;
    const float* ar = g_ao + (size_t)row * DMODEL;
    float x[4]; float s = 0.f, s2 = 0.f;
#pragma unroll
    for (int u = 0; u < 4; u++) {
        int c = tid + u * 128;
        x[u] = wr[c] + ar[c];
        s += x[u]; s2 += x[u] * x[u];
    }
#pragma unroll
    for (int o = 16; o >= 1; o >>= 1) {
        s += __shfl_xor_sync(0xffffffffu, s, o);
        s2 += __shfl_xor_sync(0xffffffffu, s2, o);
    }
    __shared__ float ss[4], ss2[4];
    int wid = tid >> 5, lane = tid & 31;
    if (lane == 0) { ss[wid] = s; ss2[wid] = s2; }
    __syncthreads();
    s = ss[0] + ss[1] + ss[2] + ss[3];
    s2 = ss2[0] + ss2[1] + ss2[2] + ss2[3];
    float mu = s * (1.f / 512.f);
    float var = s2 * (1.f / 512.f) - mu * mu;
    float rstd = rsqrtf(var + 1e-5f);
#pragma unroll
    for (int u = 0; u < 4; u++) {
        int c = tid + u * 128;
        out[(size_t)row * DMODEL + c] = (x[u] - mu) * rstd * g[c] + bta[c];
    }
}

// ---------------- launch ----------------------------------------------------
extern "C" void kernel_launch(void* const* d_in, const int* in_sizes, int n_in,
                              void* d_out, int out_size)
{
    const float* w    = (const float*)d_in[0];
    const float* r    = (const float*)d_in[1];
    const float* rwb  = (const float*)d_in[2];
    const float* rrb  = (const float*)d_in[3];
    // d_in[4] = attn_mask (causal mask computed analytically)
    const float* Wqkv = (const float*)d_in[5];
    const float* Wr   = (const float*)d_in[6];
    const float* Wo   = (const float*)d_in[7];
    const float* lng  = (const float*)d_in[8];
    const float* lnb  = (const float*)d_in[9];
    float* out = (float*)d_out;

    float *wheads, *rk, *av, *ao;
    cudaGetSymbolAddress((void**)&wheads, g_wheads);
    cudaGetSymbolAddress((void**)&rk, g_rk);
    cudaGetSymbolAddress((void**)&av, g_av);
    cudaGetSymbolAddress((void**)&ao, g_ao);

    const int ATTN_SMEM = A_TOT * (int)sizeof(float);   // ~137 KB
    cudaFuncSetAttribute(attn_mma_kernel, cudaFuncAttributeMaxDynamicSharedMemorySize, ATTN_SMEM);

    // 1) w_heads = w @ W_qkv : [8192,512] x [512,1536]   (tf32 tensor cores)
    gemm_tf32<<<dim3(1536 / 128, 8192 / 128), 256>>>(w, DMODEL, Wqkv, 3 * DMODEL, wheads, 3 * DMODEL, DMODEL);
    // 2) r_head_k = r[:,0,:] @ W_r : [1024,512] x [512,512]  (row stride BSZ*DMODEL)
    gemm_tf32<<<dim3(512 / 128, 1024 / 128), 256>>>(r, BSZ * DMODEL, Wr, DMODEL, rk, DMODEL, DMODEL);
    // 3) rank-1 bias terms
    biask_kernel<<<BSZ * NHEAD * QLEN / 8, 256>>>(rwb);
    biasr_kernel<<<NHEAD * QLEN / 8, 256>>>(rrb);
    // 4) fused causal attention with rel-shift (tensor cores)
    attn_mma_kernel<<<dim3(QLEN / 64, BSZ * NHEAD), 256, ATTN_SMEM>>>(av);
    // 5) attn_out = attn_vec @ W_o : [8192,512] x [512,512]
    gemm_tf32<<<dim3(512 / 128, 8192 / 128), 256>>>(av, DMODEL, Wo, DMODEL, ao, DMODEL, DMODEL);
    // 6) layernorm(w + attn_out)
    ln_kernel<<<QLEN * BSZ, 128>>>(w, lng, lnb, out);
}

// round 5
// speedup vs baseline: 3.1542x; 1.3470x over previous
#include <cuda_runtime.h>
#include <cstdint>
#include <cstddef>

#define QLEN 1024
#define BSZ 8
#define DMODEL 512
#define NHEAD 8
#define DHEAD 64

// ---------------- scratch (device globals: allocation-free) ----------------
__device__ float g_wheads[QLEN * BSZ * 3 * DMODEL]; // [q][b][1536]  q|k|v each n*64+d
__device__ float g_rk[QLEN * DMODEL];               // [p][n*64+d]
__device__ float g_bk[BSZ * NHEAD * QLEN];          // [(b*8+n)][j] = rwb_n . k_jbn
__device__ float g_br[NHEAD * QLEN];                // [n][p]       = rrb_n . rk_pn
__device__ float g_av[QLEN * BSZ * DMODEL];         // attn_vec [q][b][n*64+d]
__device__ float g_ao[QLEN * BSZ * DMODEL];         // attn_out

// ---------------- tf32 helpers ---------------------------------------------
__device__ __forceinline__ float to_tf32(float x) {
    uint32_t r;
    asm("cvt.rna.tf32.f32 %0, %1;" : "=r"(r) : "f"(x));
    return __uint_as_float(r);
}

__device__ __forceinline__ void mma_tf32(float* c, const uint32_t* a, const uint32_t* b) {
    asm volatile(
        "mma.sync.aligned.m16n8k8.row.col.f32.tf32.tf32.f32 "
        "{%0,%1,%2,%3}, {%4,%5,%6,%7}, {%8,%9}, {%0,%1,%2,%3};"
        : "+f"(c[0]), "+f"(c[1]), "+f"(c[2]), "+f"(c[3])
        : "r"(a[0]), "r"(a[1]), "r"(a[2]), "r"(a[3]), "r"(b[0]), "r"(b[1]));
}

// ---------------- tf32 tensor-core GEMM: C[M,N] = A[M,K] * B[K,N] ----------
__global__ __launch_bounds__(256) void gemm_tf32(
    const float* __restrict__ A, int lda,
    const float* __restrict__ B, int ldb,
    float* __restrict__ C, int ldc, int K)
{
    __shared__ float As[128][36];
    __shared__ float Bs[32][136];

    const int tid = threadIdx.x;
    const int m0 = blockIdx.y * 128, n0 = blockIdx.x * 128;
    const int warp = tid >> 5, lane = tid & 31;
    const int g = lane >> 2, tig = lane & 3;
    const int wm = (warp & 1) * 64;
    const int wn = (warp >> 1) * 32;

    float acc[4][4][4];
#pragma unroll
    for (int mf = 0; mf < 4; mf++)
#pragma unroll
        for (int nf = 0; nf < 4; nf++)
#pragma unroll
            for (int r = 0; r < 4; r++) acc[mf][nf][r] = 0.f;

    float4 ra[4], rb[4];
#pragma unroll
    for (int i = 0; i < 4; i++) {
        int idx = tid + i * 256;
        int am = idx >> 3, akq = (idx & 7) << 2;
        ra[i] = *(const float4*)&A[(size_t)(m0 + am) * lda + akq];
        int bk = idx >> 5, bn4 = (idx & 31) << 2;
        rb[i] = *(const float4*)&B[(size_t)bk * ldb + n0 + bn4];
    }

    for (int k0 = 0; k0 < K; k0 += 32) {
        __syncthreads();
#pragma unroll
        for (int i = 0; i < 4; i++) {
            int idx = tid + i * 256;
            int am = idx >> 3, akq = (idx & 7) << 2;
            As[am][akq + 0] = to_tf32(ra[i].x);
            As[am][akq + 1] = to_tf32(ra[i].y);
            As[am][akq + 2] = to_tf32(ra[i].z);
            As[am][akq + 3] = to_tf32(ra[i].w);
            int bk = idx >> 5, bn4 = (idx & 31) << 2;
            Bs[bk][bn4 + 0] = to_tf32(rb[i].x);
            Bs[bk][bn4 + 1] = to_tf32(rb[i].y);
            Bs[bk][bn4 + 2] = to_tf32(rb[i].z);
            Bs[bk][bn4 + 3] = to_tf32(rb[i].w);
        }
        __syncthreads();
        if (k0 + 32 < K) {
#pragma unroll
            for (int i = 0; i < 4; i++) {
                int idx = tid + i * 256;
                int am = idx >> 3, akq = (idx & 7) << 2;
                ra[i] = *(const float4*)&A[(size_t)(m0 + am) * lda + k0 + 32 + akq];
                int bk = idx >> 5, bn4 = (idx & 31) << 2;
                rb[i] = *(const float4*)&B[(size_t)(k0 + 32 + bk) * ldb + n0 + bn4];
            }
        }
#pragma unroll
        for (int ks = 0; ks < 4; ++ks) {
            const int kk = ks * 8;
            uint32_t af[4][4], bf[4][2];
#pragma unroll
            for (int mf = 0; mf < 4; mf++) {
                int m = wm + mf * 16 + g;
                af[mf][0] = __float_as_uint(As[m][kk + tig]);
                af[mf][1] = __float_as_uint(As[m + 8][kk + tig]);
                af[mf][2] = __float_as_uint(As[m][kk + tig + 4]);
                af[mf][3] = __float_as_uint(As[m + 8][kk + tig + 4]);
            }
#pragma unroll
            for (int nf = 0; nf < 4; nf++) {
                int n = wn + nf * 8 + g;
                bf[nf][0] = __float_as_uint(Bs[kk + tig][n]);
                bf[nf][1] = __float_as_uint(Bs[kk + tig + 4][n]);
            }
#pragma unroll
            for (int mf = 0; mf < 4; mf++)
#pragma unroll
                for (int nf = 0; nf < 4; nf++) mma_tf32(acc[mf][nf], af[mf], bf[nf]);
        }
    }

#pragma unroll
    for (int mf = 0; mf < 4; mf++) {
        int m = m0 + wm + mf * 16 + g;
#pragma unroll
        for (int nf = 0; nf < 4; nf++) {
            int n = n0 + wn + nf * 8 + tig * 2;
            float2 v0 = make_float2(acc[mf][nf][0], acc[mf][nf][1]);
            float2 v1 = make_float2(acc[mf][nf][2], acc[mf][nf][3]);
            *(float2*)&C[(size_t)m * ldc + n] = v0;
            *(float2*)&C[(size_t)(m + 8) * ldc + n] = v1;
        }
    }
}

// ---------------- bias precompute -------------------------------------------
__global__ __launch_bounds__(256) void biask_kernel(const float* __restrict__ rwb)
{
    int id = blockIdx.x * 8 + (threadIdx.x >> 5);
    int lane = threadIdx.x & 31;
    int j = id & 1023;
    int bn = id >> 10;
    int b = bn >> 3, n = bn & 7;
    const float* base = g_wheads + ((size_t)j * BSZ + b) * 1536 + 512 + n * 64;
    const float* wv = rwb + n * 64;
    float v = wv[lane] * base[lane] + wv[lane + 32] * base[lane + 32];
#pragma unroll
    for (int o = 16; o >= 1; o >>= 1) v += __shfl_xor_sync(0xffffffffu, v, o);
    if (lane == 0) g_bk[id] = v;
}

__global__ __launch_bounds__(256) void biasr_kernel(const float* __restrict__ rrb)
{
    int id = blockIdx.x * 8 + (threadIdx.x >> 5);
    int lane = threadIdx.x & 31;
    int p = id & 1023;
    int n = id >> 10;
    const float* base = g_rk + (size_t)p * DMODEL + n * 64;
    const float* wv = rrb + n * 64;
    float v = wv[lane] * base[lane] + wv[lane + 32] * base[lane + 32];
#pragma unroll
    for (int o = 16; o >= 1; o >>= 1) v += __shfl_xor_sync(0xffffffffu, v, o);
    if (lane == 0) g_br[id] = v;
}

// ---------------- tensor-core fused causal attention with rel-shift --------
// Incremental-E version: per j-tile only the NEW 64 E columns are computed;
// the low half is the previous iteration's high half (ping-pong swap).
// The RK staging buffer aliases Ss (E-mma consumes it before AC is dumped).
// SMEM float offsets:
#define A_QS   0                 // Qs  [64][68]
#define A_KS   4352              // Ks  [64][68]
#define A_VS   8704              // Vs  [64][72]
#define A_E0   13312             // E ping [64][68]
#define A_E1   17664             // E pong [64][68]
#define A_SS   22016             // Ss [64][68]  (aliases RK staging)
#define A_BKS  26368             // [64]
#define A_BRS  26432             // [128]
#define A_FAC  26560             // [64]
#define A_LINV 26624             // [64]
#define A_TOT  26688             // 104.25 KB

__global__ __launch_bounds__(256, 2) void attn_mma_kernel(float* __restrict__ av)
{
    extern __shared__ float smf[];
    float* Qs  = smf + A_QS;
    float* Ks  = smf + A_KS;
    float* Vs  = smf + A_VS;
    float* Elo = smf + A_E0;
    float* Ehi = smf + A_E1;
    float* Ss  = smf + A_SS;    // AC accum / P / RK staging alias
    float* bks = smf + A_BKS;
    float* brs = smf + A_BRS;
    float* fac = smf + A_FAC;
    float* linv= smf + A_LINV;

    const int i0 = (gridDim.x - 1 - blockIdx.x) * 64;   // heavy tiles first
    const int bn = blockIdx.y;
    const int b = bn >> 3, n = bn & 7;
    const int tid = threadIdx.x;

    // mma thread ids
    const int warp = tid >> 5, lane = tid & 31;
    const int g = lane >> 2, tig = lane & 3;
    const int wm = (warp & 3) * 16;          // 4 row-groups of 16
    const int wn = (warp >> 2) * 32;         // 2 col-groups of 32

    // softmax thread ids (16x16, 4x4 microtile)
    const int ty = tid >> 4, tx = tid & 15;
    const int tbase = 63 + 4 * (tx - ty);    // t(i,j) = tbase + j - i, in [0,126]

    // ---- prologue: load Q tile + seed Elo = Q @ RK[pmin0..pmin0+63]^T ----
    const int pmin0 = (QLEN - 64) - i0;      // >= 0, pmin0+63 <= 1023
    for (int idx = tid; idx < 64 * 16; idx += 256) {
        int r = idx >> 4, q4 = (idx & 15) << 2;
        float4 v = *(const float4*)(g_wheads + ((size_t)(i0 + r) * BSZ + b) * 1536 + n * 64 + q4);
        float* dst = Qs + r * 68 + q4;
        dst[0] = to_tf32(v.x); dst[1] = to_tf32(v.y);
        dst[2] = to_tf32(v.z); dst[3] = to_tf32(v.w);
        // RK seed rows into Ss staging
        float4 rk4 = *(const float4*)(g_rk + (size_t)(pmin0 + r) * DMODEL + n * 64 + q4);
        float* drk = Ss + r * 68 + q4;
        drk[0] = to_tf32(rk4.x); drk[1] = to_tf32(rk4.y);
        drk[2] = to_tf32(rk4.z); drk[3] = to_tf32(rk4.w);
    }
    __syncthreads();
    {
        float acc[4][4];
#pragma unroll
        for (int nf = 0; nf < 4; nf++)
#pragma unroll
            for (int r = 0; r < 4; r++) acc[nf][r] = 0.f;
#pragma unroll
        for (int kk = 0; kk < 64; kk += 8) {
            uint32_t af[4];
            af[0] = __float_as_uint(Qs[(wm + g) * 68 + kk + tig]);
            af[1] = __float_as_uint(Qs[(wm + g + 8) * 68 + kk + tig]);
            af[2] = __float_as_uint(Qs[(wm + g) * 68 + kk + tig + 4]);
            af[3] = __float_as_uint(Qs[(wm + g + 8) * 68 + kk + tig + 4]);
#pragma unroll
            for (int nf = 0; nf < 4; nf++) {
                int tt = wn + nf * 8 + g;
                uint32_t bf[2];
                bf[0] = __float_as_uint(Ss[tt * 68 + kk + tig]);
                bf[1] = __float_as_uint(Ss[tt * 68 + kk + tig + 4]);
                mma_tf32(acc[nf], af, bf);
            }
        }
#pragma unroll
        for (int nf = 0; nf < 4; nf++) {
            int tt = wn + nf * 8 + tig * 2;
            *(float2*)&Elo[(wm + g) * 68 + tt]     = make_float2(acc[nf][0], acc[nf][1]);
            *(float2*)&Elo[(wm + g + 8) * 68 + tt] = make_float2(acc[nf][2], acc[nf][3]);
        }
    }

    // softmax state + O accum (mma layout)
    float m[4], l[4];
#pragma unroll
    for (int i = 0; i < 4; i++) { m[i] = -1e30f; l[i] = 0.f; }
    float accO[4][4];
#pragma unroll
    for (int nf = 0; nf < 4; nf++)
#pragma unroll
        for (int r = 0; r < 4; r++) accO[nf][r] = 0.f;

    const int ntiles = i0 / 64 + 1;
    for (int jt = 0; jt < ntiles; ++jt) {
        const int j0 = jt * 64;
        const int pmin = (QLEN - 64) - i0 + j0;
        __syncthreads();   // prev consumers done (incl. prologue E-mma read of Ss)

        // ---- batched loads: K, V, new RK (into Ss alias), biases ----
        for (int idx = tid; idx < 64 * 16; idx += 256) {
            int r = idx >> 4, q4 = (idx & 15) << 2;
            const float* srcK = g_wheads + ((size_t)(j0 + r) * BSZ + b) * 1536 + 512 + n * 64 + q4;
            float4 k4 = *(const float4*)srcK;
            float4 v4 = *(const float4*)(srcK + 512);
            float* dK = Ks + r * 68 + q4;
            dK[0] = to_tf32(k4.x); dK[1] = to_tf32(k4.y);
            dK[2] = to_tf32(k4.z); dK[3] = to_tf32(k4.w);
            float* dV = Vs + r * 72 + q4;
            dV[0] = to_tf32(v4.x); dV[1] = to_tf32(v4.y);
            dV[2] = to_tf32(v4.z); dV[3] = to_tf32(v4.w);
            // new RK rows: p = pmin + 64 + r (clamped; clamped rows feed masked entries only)
            int p = pmin + 64 + r; if (p > QLEN - 1) p = QLEN - 1;
            float4 rk4 = *(const float4*)(g_rk + (size_t)p * DMODEL + n * 64 + q4);
            float* drk = Ss + r * 68 + q4;
            drk[0] = to_tf32(rk4.x); drk[1] = to_tf32(rk4.y);
            drk[2] = to_tf32(rk4.z); drk[3] = to_tf32(rk4.w);
        }
        if (tid < 64) bks[tid] = g_bk[((size_t)b * 8 + n) * 1024 + j0 + tid];
        if (tid < 128) { int p = pmin + tid; if (p > 1023) p = 1023; brs[tid] = g_br[n * 1024 + p]; }
        __syncthreads();

        // ---- AC = Q @ K^T (held in regs) ; Ehi = Q @ RKnew^T (dumped) ----
        float accAC[4][4], accE[4][4];
#pragma unroll
        for (int nf = 0; nf < 4; nf++)
#pragma unroll
            for (int r = 0; r < 4; r++) { accAC[nf][r] = 0.f; accE[nf][r] = 0.f; }
#pragma unroll
        for (int kk = 0; kk < 64; kk += 8) {
            uint32_t af[4];
            af[0] = __float_as_uint(Qs[(wm + g) * 68 + kk + tig]);
            af[1] = __float_as_uint(Qs[(wm + g + 8) * 68 + kk + tig]);
            af[2] = __float_as_uint(Qs[(wm + g) * 68 + kk + tig + 4]);
            af[3] = __float_as_uint(Qs[(wm + g + 8) * 68 + kk + tig + 4]);
#pragma unroll
            for (int nf = 0; nf < 4; nf++) {
                int nn = wn + nf * 8 + g;
                uint32_t bf[2];
                bf[0] = __float_as_uint(Ks[nn * 68 + kk + tig]);
                bf[1] = __float_as_uint(Ks[nn * 68 + kk + tig + 4]);
                mma_tf32(accAC[nf], af, bf);
                uint32_t ef[2];
                ef[0] = __float_as_uint(Ss[nn * 68 + kk + tig]);
                ef[1] = __float_as_uint(Ss[nn * 68 + kk + tig + 4]);
                mma_tf32(accE[nf], af, ef);
            }
        }
#pragma unroll
        for (int nf = 0; nf < 4; nf++) {
            int tt = wn + nf * 8 + tig * 2;
            *(float2*)&Ehi[(wm + g) * 68 + tt]     = make_float2(accE[nf][0], accE[nf][1]);
            *(float2*)&Ehi[(wm + g + 8) * 68 + tt] = make_float2(accE[nf][2], accE[nf][3]);
        }
        __syncthreads();   // all reads of Ss-as-RK done; Ehi visible

        // ---- dump AC into Ss ----
#pragma unroll
        for (int nf = 0; nf < 4; nf++) {
            int nn = wn + nf * 8 + tig * 2;
            *(float2*)&Ss[(wm + g) * 68 + nn]     = make_float2(accAC[nf][0], accAC[nf][1]);
            *(float2*)&Ss[(wm + g + 8) * 68 + nn] = make_float2(accAC[nf][2], accAC[nf][3]);
        }
        __syncthreads();

        // ---- softmax (16x16 layout), write P (tf32) into Ss + fac ----
        {
            float s[4][4];
#pragma unroll
            for (int i = 0; i < 4; i++) {
                int il = ty * 4 + i;
                float4 acf = *(float4*)&Ss[il * 68 + tx * 4];
                float sv[4] = {acf.x, acf.y, acf.z, acf.w};
                int gi = i0 + il;
#pragma unroll
                for (int j = 0; j < 4; j++) {
                    int t = tbase + j - i;
                    int gj = j0 + tx * 4 + j;
                    float e = (t < 64) ? Elo[il * 68 + t] : Ehi[il * 68 + t - 64];
                    float v = (sv[j] + e + bks[tx * 4 + j] + brs[t]) * 0.125f;
                    s[i][j] = (gj > gi) ? -1e30f : v;
                }
            }
#pragma unroll
            for (int i = 0; i < 4; i++) {
                float rmax = fmaxf(fmaxf(s[i][0], s[i][1]), fmaxf(s[i][2], s[i][3]));
#pragma unroll
                for (int o = 8; o >= 1; o >>= 1) rmax = fmaxf(rmax, __shfl_xor_sync(0xffffffffu, rmax, o));
                float mnew = fmaxf(m[i], rmax);
                float fc = __expf(m[i] - mnew);
                float rsum = 0.f;
#pragma unroll
                for (int j = 0; j < 4; j++) {
                    float p = __expf(s[i][j] - mnew);
                    s[i][j] = p; rsum += p;
                }
#pragma unroll
                for (int o = 8; o >= 1; o >>= 1) rsum += __shfl_xor_sync(0xffffffffu, rsum, o);
                l[i] = l[i] * fc + rsum;
                m[i] = mnew;
                if (tx == 0) fac[ty * 4 + i] = fc;
                float4 pw = make_float4(to_tf32(s[i][0]), to_tf32(s[i][1]),
                                        to_tf32(s[i][2]), to_tf32(s[i][3]));
                *(float4*)&Ss[(ty * 4 + i) * 68 + tx * 4] = pw;
            }
        }
        __syncthreads();

        // ---- rescale O accum, then O += P @ V ----
        {
            float f0 = fac[wm + g], f1 = fac[wm + g + 8];
#pragma unroll
            for (int nf = 0; nf < 4; nf++) {
                accO[nf][0] *= f0; accO[nf][1] *= f0;
                accO[nf][2] *= f1; accO[nf][3] *= f1;
            }
#pragma unroll
            for (int kk = 0; kk < 64; kk += 8) {
                uint32_t af[4];
                af[0] = __float_as_uint(Ss[(wm + g) * 68 + kk + tig]);
                af[1] = __float_as_uint(Ss[(wm + g + 8) * 68 + kk + tig]);
                af[2] = __float_as_uint(Ss[(wm + g) * 68 + kk + tig + 4]);
                af[3] = __float_as_uint(Ss[(wm + g + 8) * 68 + kk + tig + 4]);
#pragma unroll
                for (int nf = 0; nf < 4; nf++) {
                    int nn = wn + nf * 8 + g;
                    uint32_t bf[2];
                    bf[0] = __float_as_uint(Vs[(kk + tig) * 72 + nn]);
                    bf[1] = __float_as_uint(Vs[(kk + tig + 4) * 72 + nn]);
                    mma_tf32(accO[nf], af, bf);
                }
            }
        }
        // swap E ping-pong: current Ehi becomes next iteration's Elo
        float* tmp = Elo; Elo = Ehi; Ehi = tmp;
    }

    // ---- epilogue: divide by l, store ----
    if (tx == 0) {
#pragma unroll
        for (int i = 0; i < 4; i++) linv[ty * 4 + i] = 1.f / l[i];
    }
    __syncthreads();
    {
        float f0 = linv[wm + g], f1 = linv[wm + g + 8];
        int gi0 = i0 + wm + g;
        int gi1 = i0 + wm + g + 8;
#pragma unroll
        for (int nf = 0; nf < 4; nf++) {
            int nn = wn + nf * 8 + tig * 2;
            *(float2*)&av[((size_t)gi0 * BSZ + b) * DMODEL + n * 64 + nn] =
                make_float2(accO[nf][0] * f0, accO[nf][1] * f0);
            *(float2*)&av[((size_t)gi1 * BSZ + b) * DMODEL + n * 64 + nn] =
                make_float2(accO[nf][2] * f1, accO[nf][3] * f1);
        }
    }
}

// ---------------- residual + layernorm -------------------------------------
__global__ __launch_bounds__(128) void ln_kernel(
    const float* __restrict__ w, const float* __restrict__ g,
    const float* __restrict__ bta, float* __restrict__ out)
{
    int row = blockIdx.x;
    int tid = threadIdx.x;
    const float* wr = w + (size_t)row * DMODEL;
    const float* ar = g_ao + (size_t)row * DMODEL;
    float x[4]; float s = 0.f, s2 = 0.f;
#pragma unroll
    for (int u = 0; u < 4; u++) {
        int c = tid + u * 128;
        x[u] = wr[c] + ar[c];
        s += x[u]; s2 += x[u] * x[u];
    }
#pragma unroll
    for (int o = 16; o >= 1; o >>= 1) {
        s += __shfl_xor_sync(0xffffffffu, s, o);
        s2 += __shfl_xor_sync(0xffffffffu, s2, o);
    }
    __shared__ float ss[4], ss2[4];
    int wid = tid >> 5, lane = tid & 31;
    if (lane == 0) { ss[wid] = s; ss2[wid] = s2; }
    __syncthreads();
    s = ss[0] + ss[1] + ss[2] + ss[3];
    s2 = ss2[0] + ss2[1] + ss2[2] + ss2[3];
    float mu = s * (1.f / 512.f);
    float var = s2 * (1.f / 512.f) - mu * mu;
    float rstd = rsqrtf(var + 1e-5f);
#pragma unroll
    for (int u = 0; u < 4; u++) {
        int c = tid + u * 128;
        out[(size_t)row * DMODEL + c] = (x[u] - mu) * rstd * g[c] + bta[c];
    }
}

// ---------------- launch ----------------------------------------------------
extern "C" void kernel_launch(void* const* d_in, const int* in_sizes, int n_in,
                              void* d_out, int out_size)
{
    const float* w    = (const float*)d_in[0];
    const float* r    = (const float*)d_in[1];
    const float* rwb  = (const float*)d_in[2];
    const float* rrb  = (const float*)d_in[3];
    // d_in[4] = attn_mask (causal mask computed analytically)
    const float* Wqkv = (const float*)d_in[5];
    const float* Wr   = (const float*)d_in[6];
    const float* Wo   = (const float*)d_in[7];
    const float* lng  = (const float*)d_in[8];
    const float* lnb  = (const float*)d_in[9];
    float* out = (float*)d_out;

    float *wheads, *rk, *av, *ao;
    cudaGetSymbolAddress((void**)&wheads, g_wheads);
    cudaGetSymbolAddress((void**)&rk, g_rk);
    cudaGetSymbolAddress((void**)&av, g_av);
    cudaGetSymbolAddress((void**)&ao, g_ao);

    const int ATTN_SMEM = A_TOT * (int)sizeof(float);   // 104.25 KB -> 2 CTAs/SM
    cudaFuncSetAttribute(attn_mma_kernel, cudaFuncAttributeMaxDynamicSharedMemorySize, ATTN_SMEM);

    // 1) w_heads = w @ W_qkv : [8192,512] x [512,1536]   (tf32 tensor cores)
    gemm_tf32<<<dim3(1536 / 128, 8192 / 128), 256>>>(w, DMODEL, Wqkv, 3 * DMODEL, wheads, 3 * DMODEL, DMODEL);
    // 2) r_head_k = r[:,0,:] @ W_r : [1024,512] x [512,512]  (row stride BSZ*DMODEL)
    gemm_tf32<<<dim3(512 / 128, 1024 / 128), 256>>>(r, BSZ * DMODEL, Wr, DMODEL, rk, DMODEL, DMODEL);
    // 3) rank-1 bias terms
    biask_kernel<<<BSZ * NHEAD * QLEN / 8, 256>>>(rwb);
    biasr_kernel<<<NHEAD * QLEN / 8, 256>>>(rrb);
    // 4) fused causal attention with rel-shift (tensor cores, incremental E)
    attn_mma_kernel<<<dim3(QLEN / 64, BSZ * NHEAD), 256, ATTN_SMEM>>>(av);
    // 5) attn_out = attn_vec @ W_o : [8192,512] x [512,512]
    gemm_tf32<<<dim3(512 / 128, 8192 / 128), 256>>>(av, DMODEL, Wo, DMODEL, ao, DMODEL, DMODEL);
    // 6) layernorm(w + attn_out)
    ln_kernel<<<QLEN * BSZ, 128>>>(w, lng, lnb, out);
}